// round 1
// baseline (speedup 1.0000x reference)
#include <cuda_runtime.h>
#include <math.h>

#define NN 10000
#define NE 200000
#define D  256
#define EPSF 1e-6f

// ---------------- scratch (device globals: no allocation allowed) ----------
__device__ float g_u[NN * D];     // logmap0(x)
__device__ float g_h[NN * D];     // logmap0(x) @ W_lin
__device__ float g_xp[NN * D];    // hyperboloid points after bias step
__device__ float g_xtan[NN * D];  // logmap0(xp)
__device__ float g_Q[NN * D];     // xp   @ W_e1[0:256]
__device__ float g_P1[NN * D];    // xtan @ W_a1[0:256]
__device__ float g_P2[NN * D];    // xtan @ W_a1[256:512]
__device__ float g_H[NN * D];     // segment_sum(att * hidden_msg)
__device__ float g_agg[NN * D];   // g_H @ W_e2
__device__ float g_S[NN];         // segment_sum(att)

// ---------------- helpers ---------------------------------------------------
__device__ __forceinline__ float blockSum(float v, float* red) {
    int t = threadIdx.x;
    red[t] = v;
    __syncthreads();
    #pragma unroll
    for (int s = 128; s > 0; s >>= 1) {
        if (t < s) red[t] += red[t + s];
        __syncthreads();
    }
    float r = red[0];
    __syncthreads();
    return r;
}

__device__ __forceinline__ float siluf(float x) { return x / (1.f + expf(-x)); }

// ---------------- kernel 1: u = logmap0(x) ---------------------------------
__global__ void k_logmap0(const float* __restrict__ x) {
    int idx = blockIdx.x * blockDim.x + threadIdx.x;
    if (idx >= NN * D) return;
    int n = idx >> 8;          // / D
    int j = idx & (D - 1);
    float x0 = fmaxf(x[n * D], 1.f + EPSF);
    float outv;
    if (j == 0) {
        outv = 0.f;
    } else {
        float dd = acoshf(x0);
        float sc = dd / sqrtf(x0 * x0 - 1.f);
        outv = sc * x[idx];
    }
    g_u[idx] = outv;
}

// ---------------- generic SGEMM: C[M,256] = A[M,256] @ B[256,256] -----------
// BM=64, BN=64, BK=16, 256 threads, 4x4 micro-tile. N == K == 256 fixed.
__global__ __launch_bounds__(256) void sgemm64(const float* __restrict__ A,
                                               const float* __restrict__ B,
                                               float* __restrict__ C, int M) {
    __shared__ float As[16][64];
    __shared__ float Bs[16][64];
    const int K = 256, N = 256;
    int tid = threadIdx.x;
    int tr = tid >> 4;          // 0..15
    int tc = tid & 15;          // 0..15
    int rowBase = blockIdx.y * 64;
    int colBase = blockIdx.x * 64;
    float acc[4][4] = {};

    for (int kb = 0; kb < K; kb += 16) {
        #pragma unroll
        for (int l = 0; l < 4; l++) {
            int idx = tid + 256 * l;       // 0..1023 over 64x16 A tile
            int r = idx >> 4;
            int c = idx & 15;
            int gr = rowBase + r;
            As[c][r] = (gr < M) ? A[gr * K + kb + c] : 0.f;
        }
        #pragma unroll
        for (int l = 0; l < 4; l++) {
            int idx = tid + 256 * l;       // 16x64 B tile
            int r = idx >> 6;
            int c = idx & 63;
            Bs[r][c] = B[(kb + r) * N + colBase + c];
        }
        __syncthreads();
        #pragma unroll
        for (int k = 0; k < 16; k++) {
            float a[4], b[4];
            #pragma unroll
            for (int i = 0; i < 4; i++) a[i] = As[k][tr * 4 + i];
            #pragma unroll
            for (int j = 0; j < 4; j++) b[j] = Bs[k][tc * 4 + j];
            #pragma unroll
            for (int i = 0; i < 4; i++)
                #pragma unroll
                for (int j = 0; j < 4; j++) acc[i][j] += a[i] * b[j];
        }
        __syncthreads();
    }
    #pragma unroll
    for (int i = 0; i < 4; i++) {
        int gr = rowBase + tr * 4 + i;
        if (gr >= M) continue;
        #pragma unroll
        for (int j = 0; j < 4; j++)
            C[gr * N + colBase + tc * 4 + j] = acc[i][j];
    }
}

// ---------------- kernel 3: node prep --------------------------------------
// h (=proj_tan0 of GEMM result) -> xp0 = expmap0(h) -> bias parallel transport
// -> xp = expmap(xp0, u_b) -> xtan = logmap0(xp)
__global__ __launch_bounds__(256) void k_node_xp(const float* __restrict__ bias) {
    __shared__ float red[256];
    int n = blockIdx.x;
    int j = threadIdx.x;

    float hj = (j == 0) ? 0.f : g_h[n * D + j];

    // expmap0(h)
    float r1 = blockSum(hj * hj, red);
    float nn = sqrtf(fmaxf(r1, EPSF));
    float sh_n = sinhf(nn) / nn;
    float xp00 = coshf(nn);
    float xp0j = (j == 0) ? xp00 : sh_n * hj;

    // u = transp0(xp0, proj_tan0(bias))
    float bj = (j == 0) ? 0.f : bias[j];
    float c = blockSum(xp0j * bj, red);          // l_inner(xp0, bproj)
    float fac = c / (1.f + xp00);
    float uj = bj + fac * (xp0j + ((j == 0) ? 1.f : 0.f));
    float u0 = c;                                 // = 0 + fac*(xp00+1)

    // xp = expmap(xp0, u)
    float su2 = blockSum(uj * uj, red);
    float lin = su2 - 2.f * u0 * u0;
    float nu = sqrtf(fmaxf(lin, EPSF));
    float ch = coshf(nu), sh = sinhf(nu) / nu;
    float xpj = ch * xp0j + sh * uj;
    float xpc0 = ch * xp00 + sh * u0;             // component 0 (all threads)

    g_xp[n * D + j] = xpj;

    // xtan = logmap0(xp)
    float x0c = fmaxf(xpc0, 1.f + EPSF);
    float sc = acoshf(x0c) / sqrtf(x0c * x0c - 1.f);
    g_xtan[n * D + j] = (j == 0) ? 0.f : sc * xpj;
}

// ---------------- zero accumulators -----------------------------------------
__global__ void k_zero() {
    int i = blockIdx.x * blockDim.x + threadIdx.x;
    if (i < NN * D) g_H[i] = 0.f;
    if (i < NN) g_S[i] = 0.f;
}

// ---------------- edge kernel: one warp per edge ----------------------------
__global__ __launch_bounds__(256) void k_edge(
    const float* __restrict__ eattr, const int* __restrict__ row,
    const int* __restrict__ col, const float* __restrict__ emask,
    const float* __restrict__ Wa1, const float* __restrict__ ba1,
    const float* __restrict__ Wa2, const float* __restrict__ ba2,
    const float* __restrict__ We1, const float* __restrict__ be1) {
    int e = blockIdx.x * 8 + (threadIdx.x >> 5);
    if (e >= NE) return;
    int lane = threadIdx.x & 31;
    int r = row[e];
    int c = col[e];
    const float* xr = g_xp + r * D;
    const float* xc = g_xp + c * D;

    // a = 2*x0*y0 - dot(xr, xc)
    float part = 0.f;
    #pragma unroll
    for (int i = 0; i < 8; i++) {
        int j = lane + 32 * i;
        float xv = xr[j], yv = xc[j];
        part += (j == 0) ? (xv * yv) : (-xv * yv);
    }
    #pragma unroll
    for (int o = 16; o > 0; o >>= 1) part += __shfl_xor_sync(0xffffffffu, part, o);

    float a = fmaxf(part, 1.f + EPSF);
    float x0 = xr[0], y0 = xc[0];
    float dd = acoshf(a);                 // ldist
    float q = sqrtf(a * a - 1.f);
    float s = dd / q;
    float v0 = s * (y0 - a * x0);
    float beta = -v0 / (1.f + x0);
    float alpha = beta - s * a;

    float ea0 = eattr[e];
    float m = emask[e];

    // attention: hidden_a = silu(P1[r] + P2[c] + ea@Wa1_tail + ba1); logit = hidden_a . Wa2
    const float* p1 = g_P1 + r * D;
    const float* p2 = g_P2 + c * D;
    const float* wa_t0 = Wa1 + 512 * D;
    const float* wa_t1 = Wa1 + 513 * D;
    float lp = 0.f;
    #pragma unroll
    for (int i = 0; i < 8; i++) {
        int j = lane + 32 * i;
        float ha = p1[j] + p2[j] + ea0 * wa_t0[j] + dd * wa_t1[j] + ba1[j];
        lp += siluf(ha) * Wa2[j];
    }
    #pragma unroll
    for (int o = 16; o > 0; o >>= 1) lp += __shfl_xor_sync(0xffffffffu, lp, o);
    float att = m / (1.f + expf(-(lp + ba2[0])));

    // message hidden: silu(alpha*Q[r] + s*Q[c] + beta*We1[0,:] + ea@We1_tail + be1)
    const float* qr = g_Q + r * D;
    const float* qc = g_Q + c * D;
    const float* we_b = We1;              // row 0
    const float* we_t0 = We1 + 256 * D;
    const float* we_t1 = We1 + 257 * D;
    float* Hr = g_H + r * D;
    #pragma unroll
    for (int i = 0; i < 8; i++) {
        int j = lane + 32 * i;
        float hm = alpha * qr[j] + s * qc[j] + beta * we_b[j] +
                   ea0 * we_t0[j] + dd * we_t1[j] + be1[j];
        atomicAdd(Hr + j, att * siluf(hm));
    }
    if (lane == 0) atomicAdd(&g_S[r], att);
}

// ---------------- final node kernel -----------------------------------------
__global__ __launch_bounds__(256) void k_final(const float* __restrict__ be2,
                                               const float* __restrict__ lng,
                                               const float* __restrict__ lnb,
                                               float* __restrict__ out) {
    __shared__ float red[256];
    int n = blockIdx.x;
    int j = threadIdx.x;

    float Sv = g_S[n];
    float aggj = (j == 0) ? 0.f : (g_agg[n * D + j] + Sv * be2[j]);  // proj_tan0
    float xpj = g_xp[n * D + j];
    float xp0 = g_xp[n * D];

    // sup = transp0(xp, aggp)
    float cc = blockSum(xpj * aggj, red);            // l_inner(xp, aggp), aggp0=0
    float fac = cc / (1.f + xp0);
    float supj = aggj + fac * (xpj + ((j == 0) ? 1.f : 0.f));
    float sup0 = cc;

    // y = expmap(xp, sup)
    float su2 = blockSum(supj * supj, red);
    float lin = su2 - 2.f * sup0 * sup0;
    float nu = sqrtf(fmaxf(lin, EPSF));
    float ch = coshf(nu), sh = sinhf(nu) / nu;
    float yj = ch * xpj + sh * supj;
    float y0 = ch * xp0 + sh * sup0;

    // xo = logmap0(y)
    float y0c = fmaxf(y0, 1.f + EPSF);
    float sc = acoshf(y0c) / sqrtf(y0c * y0c - 1.f);
    float xoj = (j == 0) ? 0.f : sc * yj;

    // layernorm over components 1..255
    float mean = blockSum((j == 0) ? 0.f : xoj, red) * (1.f / 255.f);
    float dev = (j == 0) ? 0.f : (xoj - mean);
    float var = blockSum(dev * dev, red) * (1.f / 255.f);
    float ln = (j == 0) ? 0.f
                        : (xoj - mean) / sqrtf(var + 1e-5f) * lng[j - 1] + lnb[j - 1];

    // silu + proj_tan0 + expmap0
    float sl = (j == 0) ? 0.f : siluf(ln);
    float n2 = blockSum(sl * sl, red);
    float nn = sqrtf(fmaxf(n2, EPSF));
    out[n * D + j] = (j == 0) ? coshf(nn) : (sinhf(nn) / nn) * sl;
}

// ---------------- launch -----------------------------------------------------
extern "C" void kernel_launch(void* const* d_in, const int* in_sizes, int n_in,
                              void* d_out, int out_size) {
    const float* x     = (const float*)d_in[0];
    const float* eattr = (const float*)d_in[1];
    const int*   row   = (const int*)d_in[2];
    const int*   col   = (const int*)d_in[3];
    const float* emask = (const float*)d_in[5];
    const float* W_lin = (const float*)d_in[6];
    const float* bias  = (const float*)d_in[7];
    const float* W_e1  = (const float*)d_in[8];
    const float* b_e1  = (const float*)d_in[9];
    const float* W_e2  = (const float*)d_in[10];
    const float* b_e2  = (const float*)d_in[11];
    const float* W_a1  = (const float*)d_in[12];
    const float* b_a1  = (const float*)d_in[13];
    const float* W_a2  = (const float*)d_in[14];
    const float* b_a2  = (const float*)d_in[15];
    const float* ln_g  = (const float*)d_in[16];
    const float* ln_b  = (const float*)d_in[17];
    float* out = (float*)d_out;

    float *pu, *ph, *pxp, *pxt, *pQ, *pP1, *pP2, *pH, *pagg;
    cudaGetSymbolAddress((void**)&pu,   g_u);
    cudaGetSymbolAddress((void**)&ph,   g_h);
    cudaGetSymbolAddress((void**)&pxp,  g_xp);
    cudaGetSymbolAddress((void**)&pxt,  g_xtan);
    cudaGetSymbolAddress((void**)&pQ,   g_Q);
    cudaGetSymbolAddress((void**)&pP1,  g_P1);
    cudaGetSymbolAddress((void**)&pP2,  g_P2);
    cudaGetSymbolAddress((void**)&pH,   g_H);
    cudaGetSymbolAddress((void**)&pagg, g_agg);

    dim3 gElem((NN * D + 255) / 256);
    dim3 gGemm(4, (NN + 63) / 64);

    k_logmap0<<<gElem, 256>>>(x);
    sgemm64<<<gGemm, 256>>>(pu, W_lin, ph, NN);
    k_node_xp<<<NN, 256>>>(bias);
    sgemm64<<<gGemm, 256>>>(pxp, W_e1, pQ, NN);               // Q  = xp   @ W_e1[0:256]
    sgemm64<<<gGemm, 256>>>(pxt, W_a1, pP1, NN);              // P1 = xtan @ W_a1[0:256]
    sgemm64<<<gGemm, 256>>>(pxt, W_a1 + 256 * 256, pP2, NN);  // P2 = xtan @ W_a1[256:512]
    k_zero<<<gElem, 256>>>();
    k_edge<<<NE / 8, 256>>>(eattr, row, col, emask, W_a1, b_a1, W_a2, b_a2, W_e1, b_e1);
    sgemm64<<<gGemm, 256>>>(pH, W_e2, pagg, NN);              // agg = H @ W_e2
    k_final<<<NN, 256>>>(b_e2, ln_g, ln_b, out);
}

// round 2
// speedup vs baseline: 1.1862x; 1.1862x over previous
#include <cuda_runtime.h>
#include <math.h>

#define NN 10000
#define NE 200000
#define D  256
#define EPSF 1e-6f

typedef unsigned long long u64;

// ---------------- scratch (device globals: no allocation allowed) ----------
__device__ __align__(128) float g_u[NN * D];     // logmap0(x)
__device__ __align__(128) float g_h[NN * D];     // logmap0(x) @ W_lin
__device__ __align__(128) float g_xp[NN * D];    // hyperboloid points after bias step
__device__ __align__(128) float g_xtan[NN * D];  // logmap0(xp)
__device__ __align__(128) float g_Q[NN * D];     // xp   @ W_e1[0:256]
__device__ __align__(128) float g_P1[NN * D];    // xtan @ W_a1[0:256]
__device__ __align__(128) float g_P2[NN * D];    // xtan @ W_a1[256:512]
__device__ __align__(128) float g_H[NN * D];     // segment_sum(att * hidden_msg)
__device__ __align__(128) float g_agg[NN * D];   // g_H @ W_e2
__device__ __align__(128) float g_S[NN];         // segment_sum(att)

// ---------------- packed f32x2 helpers --------------------------------------
__device__ __forceinline__ u64 pack2(float lo, float hi) {
    u64 r; asm("mov.b64 %0,{%1,%2};" : "=l"(r) : "f"(lo), "f"(hi)); return r;
}
__device__ __forceinline__ u64 dup2(float v) {
    u64 r; asm("mov.b64 %0,{%1,%1};" : "=l"(r) : "f"(v)); return r;
}
__device__ __forceinline__ void fma2(u64& c, u64 a, u64 b) {
    asm("fma.rn.f32x2 %0,%1,%2,%0;" : "+l"(c) : "l"(a), "l"(b));
}
__device__ __forceinline__ float2 unpack2(u64 v) {
    float2 f; asm("mov.b64 {%0,%1},%2;" : "=f"(f.x), "=f"(f.y) : "l"(v)); return f;
}

// ---------------- helpers ---------------------------------------------------
__device__ __forceinline__ float blockSum(float v, float* red8) {
    #pragma unroll
    for (int o = 16; o > 0; o >>= 1) v += __shfl_xor_sync(0xffffffffu, v, o);
    __syncthreads();
    if ((threadIdx.x & 31) == 0) red8[threadIdx.x >> 5] = v;
    __syncthreads();
    float r = 0.f;
    #pragma unroll
    for (int i = 0; i < 8; i++) r += red8[i];
    return r;
}

__device__ __forceinline__ float siluf(float x) { return x / (1.f + expf(-x)); }
__device__ __forceinline__ float fsilu(float x) {
    return __fdividef(x, 1.f + __expf(-x));
}

// ---------------- kernel 1: u = logmap0(x) ---------------------------------
__global__ void k_logmap0(const float* __restrict__ x) {
    int idx = blockIdx.x * blockDim.x + threadIdx.x;
    if (idx >= NN * D) return;
    int n = idx >> 8;
    int j = idx & (D - 1);
    float x0 = fmaxf(x[n * D], 1.f + EPSF);
    float outv;
    if (j == 0) {
        outv = 0.f;
    } else {
        float dd = acoshf(x0);
        float sc = dd / sqrtf(x0 * x0 - 1.f);
        outv = sc * x[idx];
    }
    g_u[idx] = outv;
}

// ---------------- packed-FMA SGEMM: C[M,256] = A[M,256] @ B[256,256] --------
// BM=128, BN=64, BK=8, 128 threads, 8x8 micro-tile on fma.rn.f32x2.
__global__ __launch_bounds__(128) void sgemm_f2(const float* __restrict__ A,
                                                const float* __restrict__ B,
                                                float* __restrict__ C, int M) {
    __shared__ float As[2][8][128];
    __shared__ float Bs[2][8][64];
    const int K = 256, N = 256;
    int tid = threadIdx.x;
    int tr = tid >> 3;          // 0..15
    int tc = tid & 7;           // 0..7
    int rowBase = blockIdx.y * 128;
    int colBase = blockIdx.x * 64;

    // global-load mapping
    int arow = rowBase + tid;
    bool aok = arow < M;
    const float* Aptr = A + (size_t)arow * K;
    int brow = tid >> 4;              // 0..7
    int bcol = (tid & 15) * 4;        // 0..60
    const float* Bptr = B + brow * N + colBase + bcol;

    const float4 z4 = make_float4(0.f, 0.f, 0.f, 0.f);

    // prologue: tile kb=0
    float4 a0 = aok ? *(const float4*)(Aptr + 0) : z4;
    float4 a1 = aok ? *(const float4*)(Aptr + 4) : z4;
    float4 b0 = *(const float4*)(Bptr);
    As[0][0][tid] = a0.x; As[0][1][tid] = a0.y; As[0][2][tid] = a0.z; As[0][3][tid] = a0.w;
    As[0][4][tid] = a1.x; As[0][5][tid] = a1.y; As[0][6][tid] = a1.z; As[0][7][tid] = a1.w;
    *(float4*)&Bs[0][brow][bcol] = b0;
    __syncthreads();

    u64 acc[8][4];
    #pragma unroll
    for (int i = 0; i < 8; i++)
        #pragma unroll
        for (int j = 0; j < 4; j++) acc[i][j] = 0ull;

    int buf = 0;
    for (int kb = 0; kb < 32; kb++) {
        if (kb < 31) {
            const float* ap = Aptr + (kb + 1) * 8;
            a0 = aok ? *(const float4*)(ap + 0) : z4;
            a1 = aok ? *(const float4*)(ap + 4) : z4;
            b0 = *(const float4*)(Bptr + (size_t)(kb + 1) * 8 * N);
        }
        #pragma unroll
        for (int k = 0; k < 8; k++) {
            float4 av0 = *(const float4*)&As[buf][k][tr * 8];
            float4 av1 = *(const float4*)&As[buf][k][tr * 8 + 4];
            float4 bv0 = *(const float4*)&Bs[buf][k][tc * 8];
            float4 bv1 = *(const float4*)&Bs[buf][k][tc * 8 + 4];
            u64 bp0 = pack2(bv0.x, bv0.y);
            u64 bp1 = pack2(bv0.z, bv0.w);
            u64 bp2 = pack2(bv1.x, bv1.y);
            u64 bp3 = pack2(bv1.z, bv1.w);
            float am[8] = {av0.x, av0.y, av0.z, av0.w, av1.x, av1.y, av1.z, av1.w};
            #pragma unroll
            for (int i = 0; i < 8; i++) {
                u64 ad = dup2(am[i]);
                fma2(acc[i][0], ad, bp0);
                fma2(acc[i][1], ad, bp1);
                fma2(acc[i][2], ad, bp2);
                fma2(acc[i][3], ad, bp3);
            }
        }
        if (kb < 31) {
            int nb = buf ^ 1;
            As[nb][0][tid] = a0.x; As[nb][1][tid] = a0.y; As[nb][2][tid] = a0.z; As[nb][3][tid] = a0.w;
            As[nb][4][tid] = a1.x; As[nb][5][tid] = a1.y; As[nb][6][tid] = a1.z; As[nb][7][tid] = a1.w;
            *(float4*)&Bs[nb][brow][bcol] = b0;
            __syncthreads();
            buf = nb;
        }
    }

    #pragma unroll
    for (int i = 0; i < 8; i++) {
        int gr = rowBase + tr * 8 + i;
        if (gr >= M) continue;
        float2 p0 = unpack2(acc[i][0]);
        float2 p1 = unpack2(acc[i][1]);
        float2 p2 = unpack2(acc[i][2]);
        float2 p3 = unpack2(acc[i][3]);
        float4 o0 = make_float4(p0.x, p0.y, p1.x, p1.y);
        float4 o1 = make_float4(p2.x, p2.y, p3.x, p3.y);
        *(float4*)&C[(size_t)gr * N + colBase + tc * 8]     = o0;
        *(float4*)&C[(size_t)gr * N + colBase + tc * 8 + 4] = o1;
    }
}

// ---------------- kernel 3: node prep --------------------------------------
__global__ __launch_bounds__(256) void k_node_xp(const float* __restrict__ bias) {
    __shared__ float red[8];
    int n = blockIdx.x;
    int j = threadIdx.x;

    float hj = (j == 0) ? 0.f : g_h[n * D + j];

    // expmap0(h)
    float r1 = blockSum(hj * hj, red);
    float nn = sqrtf(fmaxf(r1, EPSF));
    float sh_n = sinhf(nn) / nn;
    float xp00 = coshf(nn);
    float xp0j = (j == 0) ? xp00 : sh_n * hj;

    // u = transp0(xp0, proj_tan0(bias))
    float bj = (j == 0) ? 0.f : bias[j];
    float c = blockSum(xp0j * bj, red);
    float fac = c / (1.f + xp00);
    float uj = bj + fac * (xp0j + ((j == 0) ? 1.f : 0.f));
    float u0 = c;

    // xp = expmap(xp0, u)
    float su2 = blockSum(uj * uj, red);
    float lin = su2 - 2.f * u0 * u0;
    float nu = sqrtf(fmaxf(lin, EPSF));
    float ch = coshf(nu), sh = sinhf(nu) / nu;
    float xpj = ch * xp0j + sh * uj;
    float xpc0 = ch * xp00 + sh * u0;

    g_xp[n * D + j] = xpj;

    // xtan = logmap0(xp)
    float x0c = fmaxf(xpc0, 1.f + EPSF);
    float sc = acoshf(x0c) / sqrtf(x0c * x0c - 1.f);
    g_xtan[n * D + j] = (j == 0) ? 0.f : sc * xpj;
}

// ---------------- zero accumulators -----------------------------------------
__global__ void k_zero() {
    int i = blockIdx.x * blockDim.x + threadIdx.x;
    if (i < NN * D) g_H[i] = 0.f;
    if (i < NN) g_S[i] = 0.f;
}

// ---------------- edge kernel: one warp per edge, float4 + red.v4 -----------
__global__ __launch_bounds__(256) void k_edge(
    const float* __restrict__ eattr, const int* __restrict__ row,
    const int* __restrict__ col, const float* __restrict__ emask,
    const float* __restrict__ Wa1, const float* __restrict__ ba1,
    const float* __restrict__ Wa2, const float* __restrict__ ba2,
    const float* __restrict__ We1, const float* __restrict__ be1) {
    __shared__ float sw[8][256];
    int tid = threadIdx.x;
    // stage the 8 shared weight rows once per block
    sw[0][tid] = Wa1[512 * D + tid];   // wa tail 0
    sw[1][tid] = Wa1[513 * D + tid];   // wa tail 1
    sw[2][tid] = ba1[tid];
    sw[3][tid] = Wa2[tid];
    sw[4][tid] = We1[tid];             // We1 row 0
    sw[5][tid] = We1[256 * D + tid];   // we tail 0
    sw[6][tid] = We1[257 * D + tid];   // we tail 1
    sw[7][tid] = be1[tid];
    __syncthreads();

    int e = blockIdx.x * 8 + (tid >> 5);
    int lane = tid & 31;
    int base = lane * 8;
    int r = row[e];
    int c = col[e];
    const float* xr = g_xp + (size_t)r * D;
    const float* xc = g_xp + (size_t)c * D;

    float4 xa0 = *(const float4*)(xr + base);
    float4 xa1 = *(const float4*)(xr + base + 4);
    float4 ya0 = *(const float4*)(xc + base);
    float4 ya1 = *(const float4*)(xc + base + 4);

    float part = -(xa0.x * ya0.x + xa0.y * ya0.y + xa0.z * ya0.z + xa0.w * ya0.w +
                   xa1.x * ya1.x + xa1.y * ya1.y + xa1.z * ya1.z + xa1.w * ya1.w);
    #pragma unroll
    for (int o = 16; o > 0; o >>= 1) part += __shfl_xor_sync(0xffffffffu, part, o);

    float x0 = __shfl_sync(0xffffffffu, xa0.x, 0);
    float y0 = __shfl_sync(0xffffffffu, ya0.x, 0);

    float a = fmaxf(part + 2.f * x0 * y0, 1.f + EPSF);
    float dd = acoshf(a);
    float q = sqrtf(a * a - 1.f);
    float s = dd / q;
    float v0 = s * (y0 - a * x0);
    float beta = -v0 / (1.f + x0);
    float alpha = beta - s * a;

    float ea0 = eattr[e];
    float m = emask[e];

    // attention logit
    const float* p1 = g_P1 + (size_t)r * D;
    const float* p2 = g_P2 + (size_t)c * D;
    float4 p1a = *(const float4*)(p1 + base);
    float4 p1b = *(const float4*)(p1 + base + 4);
    float4 p2a = *(const float4*)(p2 + base);
    float4 p2b = *(const float4*)(p2 + base + 4);
    float P1v[8] = {p1a.x, p1a.y, p1a.z, p1a.w, p1b.x, p1b.y, p1b.z, p1b.w};
    float P2v[8] = {p2a.x, p2a.y, p2a.z, p2a.w, p2b.x, p2b.y, p2b.z, p2b.w};

    float lp = 0.f;
    #pragma unroll
    for (int i = 0; i < 8; i++) {
        int j = base + i;
        float ha = P1v[i] + P2v[i] + ea0 * sw[0][j] + dd * sw[1][j] + sw[2][j];
        lp += fsilu(ha) * sw[3][j];
    }
    #pragma unroll
    for (int o = 16; o > 0; o >>= 1) lp += __shfl_xor_sync(0xffffffffu, lp, o);
    float att = m * __fdividef(1.f, 1.f + __expf(-(lp + ba2[0])));

    // message hidden + scatter
    const float* qr = g_Q + (size_t)r * D;
    const float* qc = g_Q + (size_t)c * D;
    float4 qa0 = *(const float4*)(qr + base);
    float4 qa1 = *(const float4*)(qr + base + 4);
    float4 qb0 = *(const float4*)(qc + base);
    float4 qb1 = *(const float4*)(qc + base + 4);
    float QR[8] = {qa0.x, qa0.y, qa0.z, qa0.w, qa1.x, qa1.y, qa1.z, qa1.w};
    float QC[8] = {qb0.x, qb0.y, qb0.z, qb0.w, qb1.x, qb1.y, qb1.z, qb1.w};

    float val[8];
    #pragma unroll
    for (int i = 0; i < 8; i++) {
        int j = base + i;
        float hm = alpha * QR[i] + s * QC[i] + beta * sw[4][j] +
                   ea0 * sw[5][j] + dd * sw[6][j] + sw[7][j];
        val[i] = att * fsilu(hm);
    }

    float* Hr = g_H + (size_t)r * D + base;
    asm volatile("red.global.add.v4.f32 [%0], {%1,%2,%3,%4};"
                 :: "l"(Hr), "f"(val[0]), "f"(val[1]), "f"(val[2]), "f"(val[3])
                 : "memory");
    asm volatile("red.global.add.v4.f32 [%0], {%1,%2,%3,%4};"
                 :: "l"(Hr + 4), "f"(val[4]), "f"(val[5]), "f"(val[6]), "f"(val[7])
                 : "memory");
    if (lane == 0) atomicAdd(&g_S[r], att);
}

// ---------------- final node kernel -----------------------------------------
__global__ __launch_bounds__(256) void k_final(const float* __restrict__ be2,
                                               const float* __restrict__ lng,
                                               const float* __restrict__ lnb,
                                               float* __restrict__ out) {
    __shared__ float red[8];
    int n = blockIdx.x;
    int j = threadIdx.x;

    float Sv = g_S[n];
    float aggj = (j == 0) ? 0.f : (g_agg[n * D + j] + Sv * be2[j]);
    float xpj = g_xp[n * D + j];
    float xp0 = g_xp[n * D];

    float cc = blockSum(xpj * aggj, red);
    float fac = cc / (1.f + xp0);
    float supj = aggj + fac * (xpj + ((j == 0) ? 1.f : 0.f));
    float sup0 = cc;

    float su2 = blockSum(supj * supj, red);
    float lin = su2 - 2.f * sup0 * sup0;
    float nu = sqrtf(fmaxf(lin, EPSF));
    float ch = coshf(nu), sh = sinhf(nu) / nu;
    float yj = ch * xpj + sh * supj;
    float y0 = ch * xp0 + sh * sup0;

    float y0c = fmaxf(y0, 1.f + EPSF);
    float sc = acoshf(y0c) / sqrtf(y0c * y0c - 1.f);
    float xoj = (j == 0) ? 0.f : sc * yj;

    float mean = blockSum((j == 0) ? 0.f : xoj, red) * (1.f / 255.f);
    float dev = (j == 0) ? 0.f : (xoj - mean);
    float var = blockSum(dev * dev, red) * (1.f / 255.f);
    float ln = (j == 0) ? 0.f
                        : (xoj - mean) / sqrtf(var + 1e-5f) * lng[j - 1] + lnb[j - 1];

    float sl = (j == 0) ? 0.f : siluf(ln);
    float n2 = blockSum(sl * sl, red);
    float nn = sqrtf(fmaxf(n2, EPSF));
    out[n * D + j] = (j == 0) ? coshf(nn) : (sinhf(nn) / nn) * sl;
}

// ---------------- launch -----------------------------------------------------
extern "C" void kernel_launch(void* const* d_in, const int* in_sizes, int n_in,
                              void* d_out, int out_size) {
    const float* x     = (const float*)d_in[0];
    const float* eattr = (const float*)d_in[1];
    const int*   row   = (const int*)d_in[2];
    const int*   col   = (const int*)d_in[3];
    const float* emask = (const float*)d_in[5];
    const float* W_lin = (const float*)d_in[6];
    const float* bias  = (const float*)d_in[7];
    const float* W_e1  = (const float*)d_in[8];
    const float* b_e1  = (const float*)d_in[9];
    const float* W_e2  = (const float*)d_in[10];
    const float* b_e2  = (const float*)d_in[11];
    const float* W_a1  = (const float*)d_in[12];
    const float* b_a1  = (const float*)d_in[13];
    const float* W_a2  = (const float*)d_in[14];
    const float* b_a2  = (const float*)d_in[15];
    const float* ln_g  = (const float*)d_in[16];
    const float* ln_b  = (const float*)d_in[17];
    float* out = (float*)d_out;

    float *pu, *ph, *pxp, *pxt, *pQ, *pP1, *pP2, *pH, *pagg;
    cudaGetSymbolAddress((void**)&pu,   g_u);
    cudaGetSymbolAddress((void**)&ph,   g_h);
    cudaGetSymbolAddress((void**)&pxp,  g_xp);
    cudaGetSymbolAddress((void**)&pxt,  g_xtan);
    cudaGetSymbolAddress((void**)&pQ,   g_Q);
    cudaGetSymbolAddress((void**)&pP1,  g_P1);
    cudaGetSymbolAddress((void**)&pP2,  g_P2);
    cudaGetSymbolAddress((void**)&pH,   g_H);
    cudaGetSymbolAddress((void**)&pagg, g_agg);

    dim3 gElem((NN * D + 255) / 256);
    dim3 gGemm(4, (NN + 127) / 128);   // BN=64 -> 4 col blocks, BM=128

    k_logmap0<<<gElem, 256>>>(x);
    sgemm_f2<<<gGemm, 128>>>(pu, W_lin, ph, NN);
    k_node_xp<<<NN, 256>>>(bias);
    sgemm_f2<<<gGemm, 128>>>(pxp, W_e1, pQ, NN);               // Q  = xp   @ W_e1[0:256]
    sgemm_f2<<<gGemm, 128>>>(pxt, W_a1, pP1, NN);              // P1 = xtan @ W_a1[0:256]
    sgemm_f2<<<gGemm, 128>>>(pxt, W_a1 + 256 * 256, pP2, NN);  // P2 = xtan @ W_a1[256:512]
    k_zero<<<gElem, 256>>>();
    k_edge<<<NE / 8, 256>>>(eattr, row, col, emask, W_a1, b_a1, W_a2, b_a2, W_e1, b_e1);
    sgemm_f2<<<gGemm, 128>>>(pH, W_e2, pagg, NN);              // agg = H @ W_e2
    k_final<<<NN, 256>>>(b_e2, ln_g, ln_b, out);
}